// round 2
// baseline (speedup 1.0000x reference)
#include <cuda_runtime.h>

#define NB 64      // batch
#define NC 64      // in channels
#define NH 32
#define NW 32
#define NOC 128
#define NL 1024
#define PH 34      // padded spatial

#define SA 72      // A smem row stride (floats), 72 % 32 == 8 -> conflict-free
#define SB 136     // B smem row stride (floats), 136 % 32 == 8
#define A_STG (32 * SA)           // A chunk: 32 c-rows x 64 b
#define B_STG (32 * SB)           // B chunk: 32 d-rows x 128 o
#define STG_ELEMS (A_STG + B_STG)
#define NSTAGE 4
#define NCHUNK 18                 // 9 taps x 2 channel halves
#define SMEM_ELEMS (NSTAGE * STG_ELEMS + NOC)
#define SMEM_BYTES (SMEM_ELEMS * 4)

// Scratch: x transposed to [c][y][x][b] (batch innermost), padded, tf32-rounded.
__device__ unsigned int g_xTp[NC * PH * PH * NB];
__device__ unsigned int g_ctr;   // dynamic work counter

// ---------------------------------------------------------------------------
// Kernel 1: transpose + pad + tf32 round.  grid (34, 64) = (y, c), 256 thr.
// Also resets the work counter for the GEMM kernel (same stream -> ordered).
// ---------------------------------------------------------------------------
__global__ void __launch_bounds__(256) transpose_pad_kernel(const float* __restrict__ x) {
    __shared__ unsigned int s[NB * 33];
    int y = blockIdx.x;
    int c = blockIdx.y;
    int tid = threadIdx.x;
    if (y == 0 && c == 0 && tid == 0) g_ctr = 0u;
    unsigned int* dst = g_xTp + (size_t)(c * PH + y) * (PH * NB);
    if (y == 0 || y == PH - 1) {
        for (int idx = tid; idx < PH * NB; idx += 256) dst[idx] = 0u;
        return;
    }
    for (int idx = tid; idx < NB * NW; idx += 256) {
        int b = idx >> 5, x0 = idx & 31;
        float v = x[(((size_t)b * NC + c) * NH + (y - 1)) * NW + x0];
        unsigned int t;
        asm("cvt.rna.tf32.f32 %0, %1;" : "=r"(t) : "f"(v));
        s[b * 33 + x0] = t;
    }
    __syncthreads();
    for (int idx = tid; idx < PH * NB; idx += 256) {
        int x0 = idx >> 6, b = idx & 63;
        dst[idx] = (x0 == 0 || x0 == PH - 1) ? 0u : s[b * 33 + (x0 - 1)];
    }
}

// ---------------------------------------------------------------------------
__device__ __forceinline__ void cp16(unsigned int saddr, const void* g) {
    asm volatile("cp.async.cg.shared.global [%0], [%1], 16;" :: "r"(saddr), "l"(g));
}
__device__ __forceinline__ unsigned int f2tf(float v) {
    unsigned int t;
    asm("cvt.rna.tf32.f32 %0, %1;" : "=r"(t) : "f"(v));
    return t;
}

// ---------------------------------------------------------------------------
// Kernel 2: persistent per-location GEMM  C[64b x 128o] = A[64b x 576d] * B
// 128 threads = 4 warps, warp tile 32x64.  K pipeline: 18 chunks of K=32,
// 4-stage cp.async double... quad-buffer with 3-chunk lookahead.
// ---------------------------------------------------------------------------
__global__ void __launch_bounds__(128, 2) lc_gemm_kernel(
    const float* __restrict__ w, const float* __restrict__ bias,
    float* __restrict__ out)
{
    extern __shared__ unsigned int sm[];
    __shared__ int s_l;
    float* sbias = (float*)(sm + NSTAGE * STG_ELEMS);
    int tid = threadIdx.x;
    int lane = tid & 31;
    int wid = tid >> 5;
    int m_base = (wid & 1) * 32;     // batch tile base
    int n_base = (wid >> 1) * 64;    // OC tile base
    unsigned int smem_base = (unsigned int)__cvta_generic_to_shared(sm);

    for (;;) {
        if (tid == 0) s_l = (int)atomicAdd(&g_ctr, 1u);
        __syncthreads();
        int l = s_l;
        if (l >= NL) break;
        int oh = l >> 5, ow = l & 31;
        const float* wl = w + (size_t)l * NOC;

        for (int o = tid; o < NOC; o += 128)
            sbias[o] = bias[(size_t)o * NL + l];

        auto load_chunk = [&](int q) {
            int st = q & (NSTAGE - 1);
            int tap = q >> 1;
            int c0 = (q & 1) << 5;
            int iy = oh + tap / 3;
            int ix = ow + tap % 3;
            unsigned int sA = smem_base + (unsigned)(st * STG_ELEMS) * 4u;
            unsigned int sB = sA + A_STG * 4;
            const unsigned int* xsrc = g_xTp + ((size_t)iy * PH + ix) * NB;
            #pragma unroll
            for (int f = 0; f < 4; ++f) {          // A: 512 float4
                int t = tid + f * 128;
                int r = t >> 4, b4 = (t & 15) << 2;
                cp16(sA + (unsigned)(r * SA + b4) * 4u,
                     xsrc + (size_t)(c0 + r) * (PH * PH * NB) + b4);
            }
            #pragma unroll
            for (int f = 0; f < 8; ++f) {          // B: 1024 float4
                int t = tid + f * 128;
                int r = t >> 5, o4 = (t & 31) << 2;
                cp16(sB + (unsigned)(r * SB + o4) * 4u,
                     wl + (size_t)((c0 + r) * 9 + tap) * (NL * NOC) + o4);
            }
            asm volatile("cp.async.commit_group;");
        };

        float acc[2][8][4];
        #pragma unroll
        for (int mt = 0; mt < 2; ++mt)
            #pragma unroll
            for (int nt = 0; nt < 8; ++nt)
                #pragma unroll
                for (int qq = 0; qq < 4; ++qq) acc[mt][nt][qq] = 0.f;

        load_chunk(0);
        load_chunk(1);
        load_chunk(2);

        for (int q = 0; q < NCHUNK; ++q) {
            if (q <= NCHUNK - 3)      asm volatile("cp.async.wait_group 2;");
            else if (q == NCHUNK - 2) asm volatile("cp.async.wait_group 1;");
            else                      asm volatile("cp.async.wait_group 0;");
            __syncthreads();
            if (q + 3 < NCHUNK) load_chunk(q + 3);

            const unsigned int* As = sm + (q & (NSTAGE - 1)) * STG_ELEMS;
            const float* Bs = (const float*)(As + A_STG);
            int kc = lane & 3, r = lane >> 2;

            #pragma unroll
            for (int k8 = 0; k8 < 4; ++k8) {
                int kb = k8 * 8;
                unsigned int a[2][4], bf[8][2];
                #pragma unroll
                for (int mt = 0; mt < 2; ++mt) {
                    int mrow = m_base + mt * 16 + r;
                    a[mt][0] = As[(kb + kc) * SA + mrow];
                    a[mt][1] = As[(kb + kc) * SA + mrow + 8];
                    a[mt][2] = As[(kb + kc + 4) * SA + mrow];
                    a[mt][3] = As[(kb + kc + 4) * SA + mrow + 8];
                }
                #pragma unroll
                for (int nt = 0; nt < 8; ++nt) {
                    int col = n_base + nt * 8 + r;
                    bf[nt][0] = f2tf(Bs[(kb + kc) * SB + col]);
                    bf[nt][1] = f2tf(Bs[(kb + kc + 4) * SB + col]);
                }
                #pragma unroll
                for (int mt = 0; mt < 2; ++mt)
                    #pragma unroll
                    for (int nt = 0; nt < 8; ++nt) {
                        asm volatile(
                            "mma.sync.aligned.m16n8k8.row.col.f32.tf32.tf32.f32 "
                            "{%0,%1,%2,%3}, {%4,%5,%6,%7}, {%8,%9}, {%0,%1,%2,%3};"
                            : "+f"(acc[mt][nt][0]), "+f"(acc[mt][nt][1]),
                              "+f"(acc[mt][nt][2]), "+f"(acc[mt][nt][3])
                            : "r"(a[mt][0]), "r"(a[mt][1]), "r"(a[mt][2]), "r"(a[mt][3]),
                              "r"(bf[nt][0]), "r"(bf[nt][1]));
                    }
            }
        }

        // Epilogue: out[b][o][l] = acc + bias[o][l]
        #pragma unroll
        for (int mt = 0; mt < 2; ++mt) {
            int r0 = m_base + mt * 16 + (lane >> 2);
            #pragma unroll
            for (int nt = 0; nt < 8; ++nt) {
                int col0 = n_base + nt * 8 + 2 * (lane & 3);
                float bz0 = sbias[col0], bz1 = sbias[col0 + 1];
                float* p0 = out + (size_t)r0 * (NOC * NL) + (size_t)col0 * NL + l;
                p0[0]                         = acc[mt][nt][0] + bz0;
                p0[NL]                        = acc[mt][nt][1] + bz1;
                p0[(size_t)8 * NOC * NL]      = acc[mt][nt][2] + bz0;
                p0[(size_t)8 * NOC * NL + NL] = acc[mt][nt][3] + bz1;
            }
        }
        __syncthreads();   // protect sbias + stage buffers before next location
    }
}

// ---------------------------------------------------------------------------
extern "C" void kernel_launch(void* const* d_in, const int* in_sizes, int n_in,
                              void* d_out, int out_size) {
    const float* x    = (const float*)d_in[0];   // (64,64,32,32)
    const float* wgt  = (const float*)d_in[1];   // (1,576,1024,128)
    const float* bias = (const float*)d_in[2];   // (1,128,32,32)
    float* out = (float*)d_out;                  // (64,128,32,32)

    cudaFuncSetAttribute(lc_gemm_kernel,
                         cudaFuncAttributeMaxDynamicSharedMemorySize, SMEM_BYTES);

    transpose_pad_kernel<<<dim3(PH, NC), 256>>>(x);
    lc_gemm_kernel<<<296, 128, SMEM_BYTES>>>(wgt, bias, out);
}

// round 3
// speedup vs baseline: 1.1206x; 1.1206x over previous
#include <cuda_runtime.h>
#include <cuda_fp16.h>

#define NB 64      // batch
#define NC 64      // in channels
#define NH 32
#define NW 32
#define NOC 128
#define NL 1024
#define PH 34      // padded spatial

#define SAK 40                    // A smem row stride in halves (80B -> conflict-free ldmatrix)
#define SB 132                    // B smem row stride in floats (132 % 32 == 4 -> conflict-free)
#define A_STG_B (64 * SAK * 2)    // 5120 B  (64 b-rows x 32 k halves + pad)
#define B_STG_B (32 * SB * 4)     // 16896 B (32 k-rows x 128 o floats + pad)
#define STG_B (A_STG_B + B_STG_B) // 22016 B
#define NSTAGE 4
#define NCHUNK 18                 // 9 taps x 2 channel halves (K=32 each)
#define SMEM_BYTES (NSTAGE * STG_B + NOC * 4)

// Scratch: x as fp16, layout [pixel=(y*34+x)][b][c], c innermost, zero-padded border.
__device__ __half g_xh[PH * PH * NB * NC];
__device__ unsigned int g_ctr;

// ---------------------------------------------------------------------------
// Kernel 0: zero the padded scratch + reset work counter.
// ---------------------------------------------------------------------------
__global__ void __launch_bounds__(512) zero_scratch_kernel() {
    if (blockIdx.x == 0 && threadIdx.x == 0) g_ctr = 0u;
    unsigned int* p = (unsigned int*)g_xh;
    size_t base = ((size_t)blockIdx.x * 512 + threadIdx.x) * 4;
    #pragma unroll
    for (int j = 0; j < 4; ++j) p[base + j] = 0u;   // total = PH*PH*NB*NC/2 u32 exactly
}

// ---------------------------------------------------------------------------
// Kernel 1: x[b][c][h][w] (f32) -> g_xh[(h+1)*34 + (w+1)][b][c] (fp16)
// grid (32 h, 8 b-groups), 256 thr.
// ---------------------------------------------------------------------------
__global__ void __launch_bounds__(256) transpose_half_kernel(const float* __restrict__ x) {
    __shared__ __half s[8][64][33];
    int h = blockIdx.x;
    int b0 = blockIdx.y * 8;
    int tid = threadIdx.x;
    // load: 8 b x 64 c x 32 w, coalesced over w
    for (int idx = tid; idx < 8 * 64 * 32; idx += 256) {
        int b = idx >> 11, c = (idx >> 5) & 63, w = idx & 31;
        float v = x[(((size_t)(b0 + b) * NC + c) * NH + h) * NW + w];
        s[b][c][w] = __float2half_rn(v);
    }
    __syncthreads();
    // write: c innermost (coalesced 128B per (w,b))
    for (int idx = tid; idx < 32 * 8 * 64; idx += 256) {
        int w = idx >> 9, b = (idx >> 6) & 7, c = idx & 63;
        g_xh[((size_t)((h + 1) * PH + (w + 1)) * NB + (b0 + b)) * NC + c] = s[b][c][w];
    }
}

// ---------------------------------------------------------------------------
__device__ __forceinline__ void cp16(unsigned int saddr, const void* g) {
    asm volatile("cp.async.cg.shared.global [%0], [%1], 16;" :: "r"(saddr), "l"(g));
}

// ---------------------------------------------------------------------------
// Kernel 2: persistent per-location GEMM, fp16 mma.sync m16n8k16, fp32 accum.
// C[64b x 128o] = A[64b x 576d] * B[576d x 128o].  256 thr = 8 warps (2x4 of 32x32).
// 18 chunks of K=32, 4-stage cp.async, 3-chunk lookahead.
// ---------------------------------------------------------------------------
__global__ void __launch_bounds__(256, 2) lc_gemm_kernel(
    const float* __restrict__ w, const float* __restrict__ bias,
    float* __restrict__ out)
{
    extern __shared__ unsigned char smraw[];
    __shared__ int s_l;
    float* sbias = (float*)(smraw + NSTAGE * STG_B);
    int tid = threadIdx.x;
    int lane = tid & 31;
    int wid = tid >> 5;
    int m_base = (wid >> 2) * 32;   // batch tile base
    int n_base = (wid & 3) * 32;    // OC tile base
    unsigned int smem_base = (unsigned int)__cvta_generic_to_shared(smraw);

    for (;;) {
        if (tid == 0) s_l = (int)atomicAdd(&g_ctr, 1u);
        __syncthreads();
        int l = s_l;
        if (l >= NL) break;
        int oh = l >> 5, ow = l & 31;
        const float* wl = w + (size_t)l * NOC;

        for (int o = tid; o < NOC; o += 256)
            sbias[o] = bias[(size_t)o * NL + l];

        auto load_chunk = [&](int q) {
            int st = q & (NSTAGE - 1);
            int tap = q >> 1;
            int c0 = (q & 1) << 5;
            int iy = oh + tap / 3;
            int ix = ow + tap % 3;
            unsigned int sA = smem_base + (unsigned)(st * STG_B);
            unsigned int sB = sA + A_STG_B;
            const __half* xsrc = g_xh + (size_t)(iy * PH + ix) * (NB * NC) + c0;
            // A: 64 b-rows x 64B (32 halves) = 256 cp16, 1 per thread
            {
                int b = tid >> 2, j = tid & 3;                 // j = 16B piece (8 halves)
                cp16(sA + (unsigned)(b * (SAK * 2) + j * 16),
                     xsrc + (size_t)b * NC + j * 8);
            }
            // B: 32 d-rows x 512B = 1024 cp16, 4 per thread
            #pragma unroll
            for (int f = 0; f < 4; ++f) {
                int t = tid + f * 256;
                int r = t >> 5, o4 = (t & 31) << 2;
                cp16(sB + (unsigned)(r * (SB * 4) + o4 * 4),
                     wl + (size_t)((c0 + r) * 9 + tap) * (NL * NOC) + o4);
            }
            asm volatile("cp.async.commit_group;");
        };

        float acc[2][4][4];
        #pragma unroll
        for (int mt = 0; mt < 2; ++mt)
            #pragma unroll
            for (int nt = 0; nt < 4; ++nt)
                #pragma unroll
                for (int qq = 0; qq < 4; ++qq) acc[mt][nt][qq] = 0.f;

        load_chunk(0);
        load_chunk(1);
        load_chunk(2);

        // ldmatrix lane mapping (fixed per thread)
        int lrow = lane & 15;             // m row within 16-block
        int lkoff = (lane >> 4) << 3;     // k offset 0 or 8 (halves)

        for (int q = 0; q < NCHUNK; ++q) {
            if (q <= NCHUNK - 3)      asm volatile("cp.async.wait_group 2;");
            else if (q == NCHUNK - 2) asm volatile("cp.async.wait_group 1;");
            else                      asm volatile("cp.async.wait_group 0;");
            __syncthreads();
            if (q + 3 < NCHUNK) load_chunk(q + 3);

            unsigned int sA = smem_base + (unsigned)((q & (NSTAGE - 1)) * STG_B);
            const float* Bs = (const float*)(smraw + (q & (NSTAGE - 1)) * STG_B + A_STG_B);

            #pragma unroll
            for (int k16 = 0; k16 < 2; ++k16) {
                unsigned int a[2][4];
                unsigned int bf[4][2];
                #pragma unroll
                for (int mt = 0; mt < 2; ++mt) {
                    unsigned int addr = sA +
                        (unsigned)((m_base + mt * 16 + lrow) * SAK + k16 * 16 + lkoff) * 2u;
                    asm volatile("ldmatrix.sync.aligned.m8n8.x4.shared.b16 "
                                 "{%0,%1,%2,%3}, [%4];"
                                 : "=r"(a[mt][0]), "=r"(a[mt][1]),
                                   "=r"(a[mt][2]), "=r"(a[mt][3])
                                 : "r"(addr));
                }
                int k0 = (lane & 3) * 2 + k16 * 16;
                #pragma unroll
                for (int nt = 0; nt < 4; ++nt) {
                    int col = n_base + nt * 8 + (lane >> 2);
                    float2 p0 = make_float2(Bs[k0 * SB + col], Bs[(k0 + 1) * SB + col]);
                    float2 p1 = make_float2(Bs[(k0 + 8) * SB + col], Bs[(k0 + 9) * SB + col]);
                    __half2 h0 = __float22half2_rn(p0);
                    __half2 h1 = __float22half2_rn(p1);
                    bf[nt][0] = *(unsigned int*)&h0;
                    bf[nt][1] = *(unsigned int*)&h1;
                }
                #pragma unroll
                for (int mt = 0; mt < 2; ++mt)
                    #pragma unroll
                    for (int nt = 0; nt < 4; ++nt) {
                        asm volatile(
                            "mma.sync.aligned.m16n8k16.row.col.f32.f16.f16.f32 "
                            "{%0,%1,%2,%3}, {%4,%5,%6,%7}, {%8,%9}, {%0,%1,%2,%3};"
                            : "+f"(acc[mt][nt][0]), "+f"(acc[mt][nt][1]),
                              "+f"(acc[mt][nt][2]), "+f"(acc[mt][nt][3])
                            : "r"(a[mt][0]), "r"(a[mt][1]), "r"(a[mt][2]), "r"(a[mt][3]),
                              "r"(bf[nt][0]), "r"(bf[nt][1]));
                    }
            }
        }

        // Epilogue: out[b][o][l] = acc + bias[o][l]
        #pragma unroll
        for (int mt = 0; mt < 2; ++mt) {
            int r0 = m_base + mt * 16 + (lane >> 2);
            #pragma unroll
            for (int nt = 0; nt < 4; ++nt) {
                int col0 = n_base + nt * 8 + 2 * (lane & 3);
                float bz0 = sbias[col0], bz1 = sbias[col0 + 1];
                float* p0 = out + (size_t)r0 * (NOC * NL) + (size_t)col0 * NL + l;
                p0[0]                         = acc[mt][nt][0] + bz0;
                p0[NL]                        = acc[mt][nt][1] + bz1;
                p0[(size_t)8 * NOC * NL]      = acc[mt][nt][2] + bz0;
                p0[(size_t)8 * NOC * NL + NL] = acc[mt][nt][3] + bz1;
            }
        }
        __syncthreads();   // protect sbias + stage buffers before next location
    }
}

// ---------------------------------------------------------------------------
extern "C" void kernel_launch(void* const* d_in, const int* in_sizes, int n_in,
                              void* d_out, int out_size) {
    const float* x    = (const float*)d_in[0];   // (64,64,32,32)
    const float* wgt  = (const float*)d_in[1];   // (1,576,1024,128)
    const float* bias = (const float*)d_in[2];   // (1,128,32,32)
    float* out = (float*)d_out;                  // (64,128,32,32)

    cudaFuncSetAttribute(lc_gemm_kernel,
                         cudaFuncAttributeMaxDynamicSharedMemorySize, SMEM_BYTES);

    // PH*PH*NB*NC halves = 4,734,976 -> /2 u32 = 2,367,488 = 1156 * 512 * 4
    zero_scratch_kernel<<<1156, 512>>>();
    transpose_half_kernel<<<dim3(NH, 8), 256>>>(x);
    lc_gemm_kernel<<<296, 256, SMEM_BYTES>>>(wgt, bias, out);
}